// round 1
// baseline (speedup 1.0000x reference)
#include <cuda_runtime.h>

#define B   128
#define IN  256
#define HS  512
#define OUT 256
#define BCHUNK 16

__device__ float g_da[B];

// ---------------------------------------------------------------------------
// K1: hactiv[b,i] = tanh( inputs[b]·i2h_w[i] + i2h_b[i]
//                         + sum_j (w[i,j] + alpha[i,j]*hebb[b,i,j]) * hidden[b,j] )
// One warp per i-row; w/alpha/i2h rows live in registers across the b-loop.
// ---------------------------------------------------------------------------
__global__ __launch_bounds__(256) void k1_hactiv(
    const float* __restrict__ inputs, const float* __restrict__ hidden,
    const float* __restrict__ hebb,   const float* __restrict__ i2h_w,
    const float* __restrict__ i2h_b,  const float* __restrict__ w,
    const float* __restrict__ alpha,  float* __restrict__ hactiv)
{
    const int warp = threadIdx.x >> 5;
    const int lane = threadIdx.x & 31;
    const int i    = blockIdx.x * 8 + warp;
    const int b0   = blockIdx.y * BCHUNK;

    __shared__ float4 sh_hidden[HS / 4];   // 128 float4 = 2 KB
    __shared__ float4 sh_input [IN / 4];   //  64 float4 = 1 KB

    // Per-lane register copies of this row's static weights.
    float4 wr[4], ar[4], iw[2];
    const float4* w4 = (const float4*)(w     + (size_t)i * HS);
    const float4* a4 = (const float4*)(alpha + (size_t)i * HS);
    const float4* x4 = (const float4*)(i2h_w + (size_t)i * IN);
#pragma unroll
    for (int k = 0; k < 4; ++k) { wr[k] = w4[lane + 32 * k]; ar[k] = a4[lane + 32 * k]; }
#pragma unroll
    for (int k = 0; k < 2; ++k) { iw[k] = x4[lane + 32 * k]; }
    const float bias = i2h_b[i];

    for (int bb = 0; bb < BCHUNK; ++bb) {
        const int b = b0 + bb;
        __syncthreads();   // protect smem from previous iteration's readers
        {
            const int t = threadIdx.x;
            if (t < 128)      sh_hidden[t]       = ((const float4*)(hidden + (size_t)b * HS))[t];
            else if (t < 192) sh_input[t - 128]  = ((const float4*)(inputs + (size_t)b * IN))[t - 128];
        }
        __syncthreads();

        const float4* hb4 = (const float4*)(hebb + ((size_t)b * HS + i) * HS);
        float s = 0.f;
#pragma unroll
        for (int k = 0; k < 4; ++k) {
            const float4 h  = hb4[lane + 32 * k];
            const float4 hd = sh_hidden[lane + 32 * k];
            s = fmaf(fmaf(ar[k].x, h.x, wr[k].x), hd.x, s);
            s = fmaf(fmaf(ar[k].y, h.y, wr[k].y), hd.y, s);
            s = fmaf(fmaf(ar[k].z, h.z, wr[k].z), hd.z, s);
            s = fmaf(fmaf(ar[k].w, h.w, wr[k].w), hd.w, s);
        }
#pragma unroll
        for (int k = 0; k < 2; ++k) {
            const float4 x = sh_input[lane + 32 * k];
            s = fmaf(iw[k].x, x.x, s); s = fmaf(iw[k].y, x.y, s);
            s = fmaf(iw[k].z, x.z, s); s = fmaf(iw[k].w, x.w, s);
        }
#pragma unroll
        for (int off = 16; off; off >>= 1) s += __shfl_xor_sync(0xffffffffu, s, off);
        if (lane == 0) hactiv[(size_t)b * HS + i] = tanhf(s + bias);
    }
}

// ---------------------------------------------------------------------------
// K2: activout = hactiv @ h2o_w.T + b ; valueout = hactiv @ h2v_w.T + b ;
//     g_da[b] = tanh(hactiv @ h2da_w.T + b).  One block per batch sample.
// ---------------------------------------------------------------------------
__global__ __launch_bounds__(256) void k2_heads(
    const float* __restrict__ hactiv, const float* __restrict__ h2o_w,
    const float* __restrict__ h2o_b,  const float* __restrict__ h2v_w,
    const float* __restrict__ h2v_b,  const float* __restrict__ h2da_w,
    const float* __restrict__ h2da_b, float* __restrict__ activout,
    float* __restrict__ valueout)
{
    const int b = blockIdx.x;
    const int t = threadIdx.x;
    __shared__ float sh[HS];
    sh[t]       = hactiv[(size_t)b * HS + t];
    sh[t + 256] = hactiv[(size_t)b * HS + t + 256];
    __syncthreads();

    // activout: one output column per thread
    const float4* wrow = (const float4*)(h2o_w + (size_t)t * HS);
    float s = 0.f;
#pragma unroll 8
    for (int f = 0; f < HS / 4; ++f) {
        const float4 wv = wrow[f];
        s = fmaf(wv.x, sh[4 * f + 0], s);
        s = fmaf(wv.y, sh[4 * f + 1], s);
        s = fmaf(wv.z, sh[4 * f + 2], s);
        s = fmaf(wv.w, sh[4 * f + 3], s);
    }
    activout[(size_t)b * OUT + t] = s + h2o_b[t];

    // valueout / da partial dots (each thread covers 2 elements)
    float pv = fmaf(h2v_w [t], sh[t], h2v_w [t + 256] * sh[t + 256]);
    float pd = fmaf(h2da_w[t], sh[t], h2da_w[t + 256] * sh[t + 256]);
#pragma unroll
    for (int off = 16; off; off >>= 1) {
        pv += __shfl_xor_sync(0xffffffffu, pv, off);
        pd += __shfl_xor_sync(0xffffffffu, pd, off);
    }
    __shared__ float rv[8], rd[8];
    if ((t & 31) == 0) { rv[t >> 5] = pv; rd[t >> 5] = pd; }
    __syncthreads();
    if (t == 0) {
        float v = 0.f, d = 0.f;
#pragma unroll
        for (int k = 0; k < 8; ++k) { v += rv[k]; d += rd[k]; }
        valueout[b] = v + h2v_b[0];
        g_da[b]     = tanhf(d + h2da_b[0]);
    }
}

// ---------------------------------------------------------------------------
// K3: hebb_new[b,i,j] = clip(hebb[b,i,j] + da[b]*hactiv[b,i]*hidden[b,j], ±1)
// Pure stream: each block handles 1024 contiguous float4 (16 KB = 8 rows).
// ---------------------------------------------------------------------------
__global__ __launch_bounds__(256) void k3_hebb(
    const float* __restrict__ hebb,   const float* __restrict__ hidden,
    const float* __restrict__ hactiv, float* __restrict__ hebb_new)
{
    const size_t base = (size_t)blockIdx.x * 1024;
    const float4* hb = (const float4*)hebb;
    const float4* hd = (const float4*)hidden;
    float4*       ob = (float4*)hebb_new;
#pragma unroll
    for (int u = 0; u < 4; ++u) {
        const size_t idx = base + (size_t)u * 256 + threadIdx.x;
        const int row = (int)(idx >> 7);        // (b*HS + i)
        const int f   = (int)(idx & 127);       // float4 index within row
        const int b   = row >> 9;
        const float coef = g_da[b] * hactiv[row];
        const float4 x = hd[b * (HS / 4) + f];
        const float4 h = hb[idx];
        float4 r;
        r.x = fminf(1.f, fmaxf(-1.f, fmaf(coef, x.x, h.x)));
        r.y = fminf(1.f, fmaxf(-1.f, fmaf(coef, x.y, h.y)));
        r.z = fminf(1.f, fmaxf(-1.f, fmaf(coef, x.z, h.z)));
        r.w = fminf(1.f, fmaxf(-1.f, fmaf(coef, x.w, h.w)));
        ob[idx] = r;
    }
}

// ---------------------------------------------------------------------------
extern "C" void kernel_launch(void* const* d_in, const int* in_sizes, int n_in,
                              void* d_out, int out_size)
{
    const float* inputs = (const float*)d_in[0];
    const float* hidden = (const float*)d_in[1];
    const float* hebb   = (const float*)d_in[2];
    const float* i2h_w  = (const float*)d_in[3];
    const float* i2h_b  = (const float*)d_in[4];
    const float* w      = (const float*)d_in[5];
    const float* alpha  = (const float*)d_in[6];
    const float* h2o_w  = (const float*)d_in[7];
    const float* h2o_b  = (const float*)d_in[8];
    const float* h2v_w  = (const float*)d_in[9];
    const float* h2v_b  = (const float*)d_in[10];
    const float* h2da_w = (const float*)d_in[11];
    const float* h2da_b = (const float*)d_in[12];

    float* out      = (float*)d_out;
    float* activout = out;                                // [B, OUT]
    float* valueout = activout + (size_t)B * OUT;         // [B, 1]
    float* hactiv   = valueout + B;                       // [B, HS]
    float* hebb_new = hactiv + (size_t)B * HS;            // [B, HS, HS]

    k1_hactiv<<<dim3(HS / 8, B / BCHUNK), 256>>>(
        inputs, hidden, hebb, i2h_w, i2h_b, w, alpha, hactiv);
    k2_heads<<<B, 256>>>(
        hactiv, h2o_w, h2o_b, h2v_w, h2v_b, h2da_w, h2da_b, activout, valueout);
    k3_hebb<<<(B * HS * (HS / 4)) / 1024, 256>>>(
        hebb, hidden, hactiv, hebb_new);
}